// round 4
// baseline (speedup 1.0000x reference)
#include <cuda_runtime.h>
#include <math.h>
#include <stdint.h>

#define NN 50000
#define D 256
#define NE 800000

// ---------------------------------------------------------------------------
// Scratch (allocation-free rule: __device__ globals)
// ---------------------------------------------------------------------------
__device__ float g_y[(size_t)NN * D];   // x + agg accumulator (layer input to GEMM)
__device__ float g_x[(size_t)NN * D];   // layer outputs
__device__ int   g_cnt[NN];             // in-degree counts
__device__ int   g_rp[NN + 1];          // CSR row pointers (by dst)
__device__ int   g_cursor[NN];          // scatter cursors
__device__ int   g_es[NE];              // permuted src indices (CSR order)
__device__ float g_ewp[NE];             // permuted edge weights (CSR order)

// ---------------------------------------------------------------------------
// CSR build: count -> scan -> scatter
// ---------------------------------------------------------------------------
__global__ void count_kernel(const int* __restrict__ dst, int* __restrict__ cnt, int ne) {
    int e = blockIdx.x * blockDim.x + threadIdx.x;
    if (e < ne) atomicAdd(cnt + dst[e], 1);
}

// single-block exclusive scan (1024 threads, shfl-based), n up to ~a few 100k
__global__ void scan_kernel(const int* __restrict__ cnt, int* __restrict__ rp, int n) {
    __shared__ int warpsum[32];
    __shared__ int s_carry;
    int t = threadIdx.x, lane = t & 31, w = t >> 5;
    if (t == 0) { s_carry = 0; rp[0] = 0; }
    __syncthreads();
    for (int base = 0; base < n; base += 1024) {
        int i = base + t;
        int v = (i < n) ? cnt[i] : 0;
        int inc = v;
#pragma unroll
        for (int o = 1; o < 32; o <<= 1) {
            int u = __shfl_up_sync(0xffffffffu, inc, o);
            if (lane >= o) inc += u;
        }
        if (lane == 31) warpsum[w] = inc;
        __syncthreads();
        if (w == 0) {
            int ws = warpsum[lane];
#pragma unroll
            for (int o = 1; o < 32; o <<= 1) {
                int u = __shfl_up_sync(0xffffffffu, ws, o);
                if (lane >= o) ws += u;
            }
            warpsum[lane] = ws;
        }
        __syncthreads();
        int carry = s_carry;
        int off = (w > 0) ? warpsum[w - 1] : 0;
        if (i < n) rp[i + 1] = carry + off + inc;
        __syncthreads();  // everyone has read s_carry / warpsum
        if (t == 1023) s_carry = carry + warpsum[31];
        __syncthreads();
    }
}

__global__ void scatter_kernel(const int* __restrict__ src, const int* __restrict__ dst,
                               const float* __restrict__ ew, const int* __restrict__ rp,
                               int* __restrict__ cursor, int* __restrict__ es,
                               float* __restrict__ ewp, int ne) {
    int e = blockIdx.x * blockDim.x + threadIdx.x;
    if (e >= ne) return;
    int r = dst[e];
    int pos = atomicAdd(cursor + r, 1);
    int idx = rp[r] + pos;
    es[idx] = src[e];
    ewp[idx] = ew[e];
}

// ---------------------------------------------------------------------------
// CSR SPMM + residual: y[i] = x[i] + sum_{e: dst=i} w_e * x[src_e]
// One warp per node; each lane owns 8 cols (2x float4) in registers.
// No atomics: each output row written exactly once.
// ---------------------------------------------------------------------------
__global__ void __launch_bounds__(256)
spmm_csr_kernel(const float* __restrict__ x, const int* __restrict__ es,
                const float* __restrict__ ewp, const int* __restrict__ rp,
                float* __restrict__ y, int n) {
    int node = (blockIdx.x * blockDim.x + threadIdx.x) >> 5;
    if (node >= n) return;
    int lane = threadIdx.x & 31;

    const float4* xr = reinterpret_cast<const float4*>(x + (size_t)node * D);
    float4 acc0 = xr[lane];
    float4 acc1 = xr[lane + 32];

    int i = rp[node], end = rp[node + 1];
    for (; i < end; i++) {
        int s = __ldg(es + i);
        float w = __ldg(ewp + i);
        const float4* sr = reinterpret_cast<const float4*>(x + (size_t)s * D);
        float4 a = sr[lane];
        float4 b = sr[lane + 32];
        acc0.x = fmaf(w, a.x, acc0.x); acc0.y = fmaf(w, a.y, acc0.y);
        acc0.z = fmaf(w, a.z, acc0.z); acc0.w = fmaf(w, a.w, acc0.w);
        acc1.x = fmaf(w, b.x, acc1.x); acc1.y = fmaf(w, b.y, acc1.y);
        acc1.z = fmaf(w, b.z, acc1.z); acc1.w = fmaf(w, b.w, acc1.w);
    }
    float4* yr = reinterpret_cast<float4*>(y + (size_t)node * D);
    yr[lane] = acc0;
    yr[lane + 32] = acc1;
}

// ---------------------------------------------------------------------------
// Fused GEMM (+bias [+LayerNorm +GELU]) : out = f(Y @ W + b)
// BM=64 x BN=256, BK=32. 256 threads = 16x16.
// A tile stored k-major transposed (pitch 65: conflict-free store+read).
// B-frags read as 4x float4 -> 8 LDS issues per 64 FFMA (FMA-bound).
// Thread (tx,ty): rows ty*4..+3, cols {g*64 + tx*4 + c : g<4, c<4}.
// ---------------------------------------------------------------------------
template<bool LNGELU>
__global__ void __launch_bounds__(256)
gemm_kernel(const float* __restrict__ Y, const float* __restrict__ W,
            const float* __restrict__ bias, const float* __restrict__ gamma,
            const float* __restrict__ beta, float* __restrict__ out, int n) {
    __shared__ float As[32][65];   // [k][m], pitch 65 -> store banks (4c4+j+m)%32 distinct
    __shared__ float Bs[32][256];  // [k][n]

    int tid = threadIdx.x;
    int tx = tid & 15;
    int ty = tid >> 4;
    int m0 = blockIdx.x * 64;

    float acc[4][16];
#pragma unroll
    for (int i = 0; i < 4; i++)
#pragma unroll
        for (int j = 0; j < 16; j++) acc[i][j] = 0.f;

    for (int k0 = 0; k0 < D; k0 += 32) {
        // A tile: 64 rows x 32 k, float4 gmem loads, transposed scalar stores
#pragma unroll
        for (int i = 0; i < 2; i++) {
            int idx = tid + 256 * i;        // 0..511
            int m = idx >> 3, c4 = idx & 7; // m 0..63, c4 0..7
            float4 v = make_float4(0.f, 0.f, 0.f, 0.f);
            int gr = m0 + m;
            if (gr < n) v = *reinterpret_cast<const float4*>(Y + (size_t)gr * D + k0 + c4 * 4);
            As[c4 * 4 + 0][m] = v.x;
            As[c4 * 4 + 1][m] = v.y;
            As[c4 * 4 + 2][m] = v.z;
            As[c4 * 4 + 3][m] = v.w;
        }
        // B tile: 32 x 256, coalesced float4
#pragma unroll
        for (int i = 0; i < 8; i++) {
            int idx = tid + 256 * i;
            int r = idx >> 6, c4 = idx & 63;
            *reinterpret_cast<float4*>(&Bs[r][c4 * 4]) =
                *reinterpret_cast<const float4*>(W + (size_t)(k0 + r) * D + c4 * 4);
        }
        __syncthreads();

#pragma unroll
        for (int kk = 0; kk < 32; kk++) {
            float a0 = As[kk][ty * 4 + 0];
            float a1 = As[kk][ty * 4 + 1];
            float a2 = As[kk][ty * 4 + 2];
            float a3 = As[kk][ty * 4 + 3];
            float4 b0 = *reinterpret_cast<const float4*>(&Bs[kk][tx * 4]);
            float4 b1 = *reinterpret_cast<const float4*>(&Bs[kk][64 + tx * 4]);
            float4 b2 = *reinterpret_cast<const float4*>(&Bs[kk][128 + tx * 4]);
            float4 b3 = *reinterpret_cast<const float4*>(&Bs[kk][192 + tx * 4]);
            float bf[16] = {b0.x, b0.y, b0.z, b0.w, b1.x, b1.y, b1.z, b1.w,
                            b2.x, b2.y, b2.z, b2.w, b3.x, b3.y, b3.z, b3.w};
            float a[4] = {a0, a1, a2, a3};
#pragma unroll
            for (int i = 0; i < 4; i++)
#pragma unroll
                for (int j = 0; j < 16; j++) acc[i][j] = fmaf(a[i], bf[j], acc[i][j]);
        }
        __syncthreads();
    }

    // Epilogue. col(j) = (j>>2)*64 + tx*4 + (j&3)
#pragma unroll
    for (int i = 0; i < 4; i++) {
        int gr = m0 + ty * 4 + i;
        float v[16];
        if (LNGELU) {
            float s = 0.f;
#pragma unroll
            for (int j = 0; j < 16; j++) {
                int col = ((j >> 2) << 6) + tx * 4 + (j & 3);
                v[j] = acc[i][j] + __ldg(bias + col);
                s += v[j];
            }
#pragma unroll
            for (int o = 1; o < 16; o <<= 1) s += __shfl_xor_sync(0xffffffffu, s, o);
            float mean = s * (1.f / 256.f);
            float s2 = 0.f;
#pragma unroll
            for (int j = 0; j < 16; j++) {
                float dv = v[j] - mean;
                s2 += dv * dv;
            }
#pragma unroll
            for (int o = 1; o < 16; o <<= 1) s2 += __shfl_xor_sync(0xffffffffu, s2, o);
            float rstd = rsqrtf(s2 * (1.f / 256.f) + 1e-5f);
            if (gr < n) {
#pragma unroll
                for (int j = 0; j < 16; j++) {
                    int col = ((j >> 2) << 6) + tx * 4 + (j & 3);
                    float t = (v[j] - mean) * rstd * __ldg(gamma + col) + __ldg(beta + col);
                    float ge = 0.5f * t * (1.f + erff(t * 0.70710678118654752f));
                    out[(size_t)gr * D + col] = ge;
                }
            }
        } else {
            if (gr < n) {
#pragma unroll
                for (int j = 0; j < 16; j++) {
                    int col = ((j >> 2) << 6) + tx * 4 + (j & 3);
                    out[(size_t)gr * D + col] = acc[i][j] + __ldg(bias + col);
                }
            }
        }
    }
}

// ---------------------------------------------------------------------------
// launch
// ---------------------------------------------------------------------------
extern "C" void kernel_launch(void* const* d_in, const int* in_sizes, int n_in,
                              void* d_out, int out_size) {
    const float* node = (const float*)d_in[0];
    const int*   src  = (const int*)d_in[1];
    const int*   dst  = (const int*)d_in[2];
    const float* ew   = (const float*)d_in[3];
    const float* W1   = (const float*)d_in[4];
    const float* b1   = (const float*)d_in[5];
    const float* g1   = (const float*)d_in[6];
    const float* be1  = (const float*)d_in[7];
    const float* W2   = (const float*)d_in[8];
    const float* b2   = (const float*)d_in[9];
    const float* g2   = (const float*)d_in[10];
    const float* be2  = (const float*)d_in[11];
    const float* Wp   = (const float*)d_in[12];
    const float* bp   = (const float*)d_in[13];
    float* out = (float*)d_out;

    int n = in_sizes[0] / D;
    int nedges = in_sizes[1];

    float *y, *x, *ewp;
    int *cnt, *rp, *cursor, *es;
    cudaGetSymbolAddress((void**)&y, g_y);
    cudaGetSymbolAddress((void**)&x, g_x);
    cudaGetSymbolAddress((void**)&cnt, g_cnt);
    cudaGetSymbolAddress((void**)&rp, g_rp);
    cudaGetSymbolAddress((void**)&cursor, g_cursor);
    cudaGetSymbolAddress((void**)&es, g_es);
    cudaGetSymbolAddress((void**)&ewp, g_ewp);

    int edgeBlocks = (nedges + 255) / 256;
    int spmmBlocks = (n + 7) / 8;          // 8 warps (nodes) per 256-thread block
    int gemmBlocks = (n + 63) / 64;

    // ---- CSR build (once per launch; reused by both SPMMs) ----
    cudaMemsetAsync(cnt, 0, (size_t)n * sizeof(int));
    cudaMemsetAsync(cursor, 0, (size_t)n * sizeof(int));
    count_kernel<<<edgeBlocks, 256>>>(dst, cnt, nedges);
    scan_kernel<<<1, 1024>>>(cnt, rp, n);
    scatter_kernel<<<edgeBlocks, 256>>>(src, dst, ew, rp, cursor, es, ewp, nedges);

    // ---- Layer 1 ----
    spmm_csr_kernel<<<spmmBlocks, 256>>>(node, es, ewp, rp, y, n);
    gemm_kernel<true><<<gemmBlocks, 256>>>(y, W1, b1, g1, be1, x, n);

    // ---- Layer 2 ----
    spmm_csr_kernel<<<spmmBlocks, 256>>>(x, es, ewp, rp, y, n);
    gemm_kernel<true><<<gemmBlocks, 256>>>(y, W2, b2, g2, be2, x, n);

    // ---- Projection ----
    gemm_kernel<false><<<gemmBlocks, 256>>>(x, Wp, bp, nullptr, nullptr, out, n);
}

// round 5
// speedup vs baseline: 1.2248x; 1.2248x over previous
#include <cuda_runtime.h>
#include <math.h>
#include <stdint.h>

#define NN 50000
#define D 256
#define NE 800000
#define PAD 64
#define SPILL_MAX 8192

// ---------------------------------------------------------------------------
// Scratch (allocation-free rule: __device__ globals)
// ---------------------------------------------------------------------------
__device__ float g_y[(size_t)NN * D];        // x + agg accumulator
__device__ float g_x[(size_t)NN * D];        // layer outputs
__device__ int   g_cnt[NN];                  // per-node edge counts (cursor)
__device__ int2  g_esw[(size_t)NN * PAD];    // packed (src, weight_bits) buckets
__device__ int4  g_spill[SPILL_MAX];         // overflow edges (src, dst, wbits, 0)
__device__ int   g_spill_cnt;

// ---------------------------------------------------------------------------
// Bucket build: one pass. pos = atomicAdd(cnt[dst]); write packed edge.
// ---------------------------------------------------------------------------
__global__ void bucket_kernel(const int* __restrict__ src, const int* __restrict__ dst,
                              const float* __restrict__ ew, int* __restrict__ cnt,
                              int2* __restrict__ esw, int4* __restrict__ spill,
                              int* __restrict__ spill_cnt, int ne) {
    int e = blockIdx.x * blockDim.x + threadIdx.x;
    if (e >= ne) return;
    int d = dst[e];
    int s = src[e];
    int wb = __float_as_int(ew[e]);
    int pos = atomicAdd(cnt + d, 1);
    if (pos < PAD) {
        esw[(size_t)d * PAD + pos] = make_int2(s, wb);
    } else {
        int sp = atomicAdd(spill_cnt, 1);
        if (sp < SPILL_MAX) spill[sp] = make_int4(s, d, wb, 0);
    }
}

// ---------------------------------------------------------------------------
// SPMM + residual: y[i] = x[i] + sum_e w_e * x[src_e].  One warp per node,
// lanes own 8 cols (2x float4) in registers. No atomics on the main path.
// ---------------------------------------------------------------------------
__global__ void __launch_bounds__(256)
spmm_pad_kernel(const float* __restrict__ x, const int2* __restrict__ esw,
                const int* __restrict__ cnt, float* __restrict__ y, int n) {
    int node = (blockIdx.x * blockDim.x + threadIdx.x) >> 5;
    if (node >= n) return;
    int lane = threadIdx.x & 31;

    const float4* xr = reinterpret_cast<const float4*>(x + (size_t)node * D);
    float4 acc0 = xr[lane];
    float4 acc1 = xr[lane + 32];

    int m = cnt[node];
    if (m > PAD) m = PAD;
    const int2* bp = esw + (size_t)node * PAD;
    for (int j = 0; j < m; j++) {
        int2 p = __ldg(bp + j);
        float w = __int_as_float(p.y);
        const float4* sr = reinterpret_cast<const float4*>(x + (size_t)p.x * D);
        float4 a = sr[lane];
        float4 b = sr[lane + 32];
        acc0.x = fmaf(w, a.x, acc0.x); acc0.y = fmaf(w, a.y, acc0.y);
        acc0.z = fmaf(w, a.z, acc0.z); acc0.w = fmaf(w, a.w, acc0.w);
        acc1.x = fmaf(w, b.x, acc1.x); acc1.y = fmaf(w, b.y, acc1.y);
        acc1.z = fmaf(w, b.z, acc1.z); acc1.w = fmaf(w, b.w, acc1.w);
    }
    float4* yr = reinterpret_cast<float4*>(y + (size_t)node * D);
    yr[lane] = acc0;
    yr[lane + 32] = acc1;
}

// Spill fixup: one warp per overflow edge, vector reduction add into y.
__device__ __forceinline__ void red_add_v4(float* p, float4 v) {
    asm volatile("red.global.add.v4.f32 [%0], {%1, %2, %3, %4};"
                 :: "l"(p), "f"(v.x), "f"(v.y), "f"(v.z), "f"(v.w) : "memory");
}

__global__ void spill_kernel(const float* __restrict__ x, const int4* __restrict__ spill,
                             const int* __restrict__ spill_cnt, float* __restrict__ y) {
    int cntv = *spill_cnt;
    if (cntv > SPILL_MAX) cntv = SPILL_MAX;
    int nwarps = (gridDim.x * blockDim.x) >> 5;
    int lane = threadIdx.x & 31;
    for (int idx = (blockIdx.x * blockDim.x + threadIdx.x) >> 5; idx < cntv; idx += nwarps) {
        int4 e = spill[idx];
        float w = __int_as_float(e.z);
        const float4* sr = reinterpret_cast<const float4*>(x + (size_t)e.x * D);
        float* yr = y + (size_t)e.y * D;
        float4 a = sr[lane];
        float4 b = sr[lane + 32];
        a.x *= w; a.y *= w; a.z *= w; a.w *= w;
        b.x *= w; b.y *= w; b.z *= w; b.w *= w;
        red_add_v4(yr + lane * 4, a);
        red_add_v4(yr + 128 + lane * 4, b);
    }
}

// ---------------------------------------------------------------------------
// Double-buffered SGEMM + bias [+ LayerNorm + GELU].
// BM=128, BN=256, BK=16. 512 threads, 8x8 per thread.
// Inner loop: 4x LDS.128 + 64 FFMA (94% FMA issue efficiency).
// Warp ty owns rows ty*8..ty*8+7 entirely -> LN via full-warp shfl.
// ---------------------------------------------------------------------------
#define AP 132                         // A pitch (floats)
#define ASZ (16 * AP)                  // one A buffer
#define BSZ (16 * 256)                 // one B buffer
#define SMEM_BYTES ((2 * ASZ + 2 * BSZ) * 4)

template<bool LNGELU>
__global__ void __launch_bounds__(512, 1)
gemm_kernel(const float* __restrict__ Y, const float* __restrict__ W,
            const float* __restrict__ bias, const float* __restrict__ gamma,
            const float* __restrict__ beta, float* __restrict__ out, int n) {
    extern __shared__ float smem[];
    float* as_base = smem;                 // [buf][k][m] pitch AP
    float* bs_base = smem + 2 * ASZ;       // [buf][k][c]

    int tid = threadIdx.x;
    int tx = tid & 31;
    int ty = tid >> 5;
    int m0 = blockIdx.x * 128;

    // load-role indices
    int arow = tid >> 2, aq = tid & 3;     // A: row 0..127, float4 quarter of 16-k row
    int brow = tid >> 6, bc4 = tid & 63;   // B: rows brow, brow+8; col4

    float acc[8][8];
#pragma unroll
    for (int i = 0; i < 8; i++)
#pragma unroll
        for (int j = 0; j < 8; j++) acc[i][j] = 0.f;

    float4 areg, breg0, breg1;
    // prologue: fetch tile 0
    {
        int gr = m0 + arow;
        areg = (gr < n) ? *reinterpret_cast<const float4*>(Y + (size_t)gr * D + aq * 4)
                        : make_float4(0.f, 0.f, 0.f, 0.f);
        breg0 = *reinterpret_cast<const float4*>(W + (size_t)brow * D + bc4 * 4);
        breg1 = *reinterpret_cast<const float4*>(W + (size_t)(brow + 8) * D + bc4 * 4);
    }
    // store tile 0 -> buf 0
    as_base[(aq * 4 + 0) * AP + arow] = areg.x;
    as_base[(aq * 4 + 1) * AP + arow] = areg.y;
    as_base[(aq * 4 + 2) * AP + arow] = areg.z;
    as_base[(aq * 4 + 3) * AP + arow] = areg.w;
    *reinterpret_cast<float4*>(bs_base + brow * 256 + bc4 * 4) = breg0;
    *reinterpret_cast<float4*>(bs_base + (brow + 8) * 256 + bc4 * 4) = breg1;
    __syncthreads();

    int buf = 0;
#pragma unroll
    for (int t = 0; t < 16; t++) {
        if (t < 15) {
            int k0 = (t + 1) * 16;
            int gr = m0 + arow;
            areg = (gr < n) ? *reinterpret_cast<const float4*>(Y + (size_t)gr * D + k0 + aq * 4)
                            : make_float4(0.f, 0.f, 0.f, 0.f);
            breg0 = *reinterpret_cast<const float4*>(W + (size_t)(k0 + brow) * D + bc4 * 4);
            breg1 = *reinterpret_cast<const float4*>(W + (size_t)(k0 + brow + 8) * D + bc4 * 4);
        }

        const float* ab = as_base + buf * ASZ;
        const float* bb = bs_base + buf * BSZ;
#pragma unroll
        for (int kk = 0; kk < 16; kk++) {
            float4 a0 = *reinterpret_cast<const float4*>(ab + kk * AP + ty * 8);
            float4 a1 = *reinterpret_cast<const float4*>(ab + kk * AP + ty * 8 + 4);
            float4 b0 = *reinterpret_cast<const float4*>(bb + kk * 256 + tx * 4);
            float4 b1 = *reinterpret_cast<const float4*>(bb + kk * 256 + 128 + tx * 4);
            float a[8] = {a0.x, a0.y, a0.z, a0.w, a1.x, a1.y, a1.z, a1.w};
            float bfr[8] = {b0.x, b0.y, b0.z, b0.w, b1.x, b1.y, b1.z, b1.w};
#pragma unroll
            for (int i = 0; i < 8; i++)
#pragma unroll
                for (int j = 0; j < 8; j++) acc[i][j] = fmaf(a[i], bfr[j], acc[i][j]);
        }

        if (t < 15) {
            int nb = buf ^ 1;
            float* aw = as_base + nb * ASZ;
            float* bw = bs_base + nb * BSZ;
            aw[(aq * 4 + 0) * AP + arow] = areg.x;
            aw[(aq * 4 + 1) * AP + arow] = areg.y;
            aw[(aq * 4 + 2) * AP + arow] = areg.z;
            aw[(aq * 4 + 3) * AP + arow] = areg.w;
            *reinterpret_cast<float4*>(bw + brow * 256 + bc4 * 4) = breg0;
            *reinterpret_cast<float4*>(bw + (brow + 8) * 256 + bc4 * 4) = breg1;
            __syncthreads();
            buf = nb;
        }
    }

    // Epilogue: col(j) = (j>>2)*128 + tx*4 + (j&3); rows ty*8+i, warp-owned.
#pragma unroll
    for (int i = 0; i < 8; i++) {
        int gr = m0 + ty * 8 + i;
        if (LNGELU) {
            float v[8];
            float s = 0.f;
#pragma unroll
            for (int j = 0; j < 8; j++) {
                int col = ((j >> 2) << 7) + tx * 4 + (j & 3);
                v[j] = acc[i][j] + __ldg(bias + col);
                s += v[j];
            }
#pragma unroll
            for (int o = 1; o < 32; o <<= 1) s += __shfl_xor_sync(0xffffffffu, s, o);
            float mean = s * (1.f / 256.f);
            float s2 = 0.f;
#pragma unroll
            for (int j = 0; j < 8; j++) {
                float dv = v[j] - mean;
                s2 += dv * dv;
            }
#pragma unroll
            for (int o = 1; o < 32; o <<= 1) s2 += __shfl_xor_sync(0xffffffffu, s2, o);
            float rstd = rsqrtf(s2 * (1.f / 256.f) + 1e-5f);
            if (gr < n) {
#pragma unroll
                for (int j = 0; j < 8; j++) {
                    int col = ((j >> 2) << 7) + tx * 4 + (j & 3);
                    float tv = (v[j] - mean) * rstd * __ldg(gamma + col) + __ldg(beta + col);
                    float ge = 0.5f * tv * (1.f + erff(tv * 0.70710678118654752f));
                    out[(size_t)gr * D + col] = ge;
                }
            }
        } else {
            if (gr < n) {
#pragma unroll
                for (int j = 0; j < 8; j++) {
                    int col = ((j >> 2) << 7) + tx * 4 + (j & 3);
                    out[(size_t)gr * D + col] = acc[i][j] + __ldg(bias + col);
                }
            }
        }
    }
}

// ---------------------------------------------------------------------------
// launch
// ---------------------------------------------------------------------------
extern "C" void kernel_launch(void* const* d_in, const int* in_sizes, int n_in,
                              void* d_out, int out_size) {
    const float* node = (const float*)d_in[0];
    const int*   src  = (const int*)d_in[1];
    const int*   dst  = (const int*)d_in[2];
    const float* ew   = (const float*)d_in[3];
    const float* W1   = (const float*)d_in[4];
    const float* b1   = (const float*)d_in[5];
    const float* g1   = (const float*)d_in[6];
    const float* be1  = (const float*)d_in[7];
    const float* W2   = (const float*)d_in[8];
    const float* b2   = (const float*)d_in[9];
    const float* g2   = (const float*)d_in[10];
    const float* be2  = (const float*)d_in[11];
    const float* Wp   = (const float*)d_in[12];
    const float* bp   = (const float*)d_in[13];
    float* out = (float*)d_out;

    int n = in_sizes[0] / D;
    int nedges = in_sizes[1];

    float *y, *x;
    int *cnt, *spill_cnt;
    int2* esw;
    int4* spill;
    cudaGetSymbolAddress((void**)&y, g_y);
    cudaGetSymbolAddress((void**)&x, g_x);
    cudaGetSymbolAddress((void**)&cnt, g_cnt);
    cudaGetSymbolAddress((void**)&esw, g_esw);
    cudaGetSymbolAddress((void**)&spill, g_spill);
    cudaGetSymbolAddress((void**)&spill_cnt, g_spill_cnt);

    static bool attr_set = false;
    if (!attr_set) {
        cudaFuncSetAttribute(gemm_kernel<true>, cudaFuncAttributeMaxDynamicSharedMemorySize, SMEM_BYTES);
        cudaFuncSetAttribute(gemm_kernel<false>, cudaFuncAttributeMaxDynamicSharedMemorySize, SMEM_BYTES);
        attr_set = true;
    }

    int edgeBlocks = (nedges + 255) / 256;
    int spmmBlocks = (n + 7) / 8;
    int gemmBlocks = (n + 127) / 128;

    // ---- bucket build (single pass, reused by both SPMMs) ----
    cudaMemsetAsync(cnt, 0, (size_t)n * sizeof(int));
    cudaMemsetAsync(spill_cnt, 0, sizeof(int));
    bucket_kernel<<<edgeBlocks, 256>>>(src, dst, ew, cnt, esw, spill, spill_cnt, nedges);

    // ---- Layer 1 ----
    spmm_pad_kernel<<<spmmBlocks, 256>>>(node, esw, cnt, y, n);
    spill_kernel<<<16, 256>>>(node, spill, spill_cnt, y);
    gemm_kernel<true><<<gemmBlocks, 512, SMEM_BYTES>>>(y, W1, b1, g1, be1, x, n);

    // ---- Layer 2 ----
    spmm_pad_kernel<<<spmmBlocks, 256>>>(x, esw, cnt, y, n);
    spill_kernel<<<16, 256>>>(x, spill, spill_cnt, y);
    gemm_kernel<true><<<gemmBlocks, 512, SMEM_BYTES>>>(y, W2, b2, g2, be2, x, n);

    // ---- Projection ----
    gemm_kernel<false><<<gemmBlocks, 512, SMEM_BYTES>>>(x, Wp, bp, nullptr, nullptr, out, n);
}

// round 6
// speedup vs baseline: 2.6665x; 2.1772x over previous
#include <cuda_runtime.h>
#include <cuda_bf16.h>
#include <math.h>
#include <stdint.h>

#define NN 50000
#define D 256
#define NE 800000
#define PAD 64
#define SPILL_MAX 8192

// ---------------------------------------------------------------------------
// Scratch (allocation-free rule: __device__ globals)
// ---------------------------------------------------------------------------
__device__ __nv_bfloat16 g_ah[(size_t)NN * D];   // activation hi plane
__device__ __nv_bfloat16 g_al[(size_t)NN * D];   // activation lo plane
__device__ __nv_bfloat16 g_ch[(size_t)NN * D];   // second plane pair
__device__ __nv_bfloat16 g_cl[(size_t)NN * D];
__device__ float g_x[(size_t)NN * D];            // fp32 layer-1 output (SPMM2 input)
__device__ int   g_cnt[NN];
__device__ int2  g_esw[(size_t)NN * PAD];
__device__ int4  g_spill[SPILL_MAX];
__device__ int   g_spill_cnt;
__device__ uint4 g_bp1[16 * 32 * 32];            // fragment-packed weights hi|lo
__device__ uint4 g_bp2[16 * 32 * 32];
__device__ uint4 g_bp3[16 * 32 * 32];

__device__ __forceinline__ uint32_t pk(__nv_bfloat16 a, __nv_bfloat16 b) {
    return (uint32_t)__bfloat16_as_ushort(a) | ((uint32_t)__bfloat16_as_ushort(b) << 16);
}

// ---------------------------------------------------------------------------
// Bucket build (one pass)
// ---------------------------------------------------------------------------
__global__ void bucket_kernel(const int* __restrict__ src, const int* __restrict__ dst,
                              const float* __restrict__ ew, int* __restrict__ cnt,
                              int2* __restrict__ esw, int4* __restrict__ spill,
                              int* __restrict__ spill_cnt, int ne) {
    int e = blockIdx.x * blockDim.x + threadIdx.x;
    if (e >= ne) return;
    int d = dst[e];
    int s = src[e];
    int wb = __float_as_int(ew[e]);
    int pos = atomicAdd(cnt + d, 1);
    if (pos < PAD) {
        esw[(size_t)d * PAD + pos] = make_int2(s, wb);
    } else {
        int sp = atomicAdd(spill_cnt, 1);
        if (sp < SPILL_MAX) spill[sp] = make_int4(s, d, wb, 0);
    }
}

// ---------------------------------------------------------------------------
// Weight prep: W[k][n] fp32 -> fragment-ordered packed hi/lo uint4.
// idx = (kt*32 + ntile)*32 + lane ; lane: t=lane&3 (k-pair), g=lane>>2 (n).
// uint4 = { hi(k=2t,2t+1), hi(k=2t+8,2t+9), lo(k=2t,2t+1), lo(k=2t+8,2t+9) }
// ---------------------------------------------------------------------------
__global__ void prep_b_kernel(const float* __restrict__ W, uint4* __restrict__ bp) {
    int idx = blockIdx.x * 256 + threadIdx.x;
    if (idx >= 16 * 32 * 32) return;
    int lane = idx & 31, ntg = (idx >> 5) & 31, kt = idx >> 10;
    int t = lane & 3, g = lane >> 2;
    int nn = ntg * 8 + g;
    int k0 = kt * 16 + 2 * t;
    float w0 = W[(size_t)k0 * D + nn];
    float w1 = W[(size_t)(k0 + 1) * D + nn];
    float w2 = W[(size_t)(k0 + 8) * D + nn];
    float w3 = W[(size_t)(k0 + 9) * D + nn];
    __nv_bfloat16 h0 = __float2bfloat16_rn(w0), h1 = __float2bfloat16_rn(w1);
    __nv_bfloat16 h2 = __float2bfloat16_rn(w2), h3 = __float2bfloat16_rn(w3);
    __nv_bfloat16 l0 = __float2bfloat16_rn(w0 - __bfloat162float(h0));
    __nv_bfloat16 l1 = __float2bfloat16_rn(w1 - __bfloat162float(h1));
    __nv_bfloat16 l2 = __float2bfloat16_rn(w2 - __bfloat162float(h2));
    __nv_bfloat16 l3 = __float2bfloat16_rn(w3 - __bfloat162float(h3));
    uint4 v;
    v.x = pk(h0, h1); v.y = pk(h2, h3);
    v.z = pk(l0, l1); v.w = pk(l2, l3);
    bp[idx] = v;
}

// ---------------------------------------------------------------------------
// SPMM + residual -> bf16 hi/lo planes. One warp per node, no atomics.
// Spill edges handled in-kernel by deterministic scan (expected empty).
// ---------------------------------------------------------------------------
__device__ __forceinline__ void wr_split(__nv_bfloat16* Hp, __nv_bfloat16* Lp, float4 a) {
    __nv_bfloat16 h0 = __float2bfloat16_rn(a.x), h1 = __float2bfloat16_rn(a.y);
    __nv_bfloat16 h2 = __float2bfloat16_rn(a.z), h3 = __float2bfloat16_rn(a.w);
    __nv_bfloat16 l0 = __float2bfloat16_rn(a.x - __bfloat162float(h0));
    __nv_bfloat16 l1 = __float2bfloat16_rn(a.y - __bfloat162float(h1));
    __nv_bfloat16 l2 = __float2bfloat16_rn(a.z - __bfloat162float(h2));
    __nv_bfloat16 l3 = __float2bfloat16_rn(a.w - __bfloat162float(h3));
    uint2 uh, ul;
    uh.x = pk(h0, h1); uh.y = pk(h2, h3);
    ul.x = pk(l0, l1); ul.y = pk(l2, l3);
    *reinterpret_cast<uint2*>(Hp) = uh;
    *reinterpret_cast<uint2*>(Lp) = ul;
}

__global__ void __launch_bounds__(256)
spmm_kernel(const float* __restrict__ x, const int2* __restrict__ esw,
            const int* __restrict__ cnt, const int4* __restrict__ spill,
            const int* __restrict__ spill_cnt,
            __nv_bfloat16* __restrict__ Ah, __nv_bfloat16* __restrict__ Al, int n) {
    int node = (blockIdx.x * blockDim.x + threadIdx.x) >> 5;
    if (node >= n) return;
    int lane = threadIdx.x & 31;

    const float4* xr = reinterpret_cast<const float4*>(x + (size_t)node * D);
    float4 acc0 = xr[lane];
    float4 acc1 = xr[lane + 32];

    int mraw = cnt[node];
    int m = mraw < PAD ? mraw : PAD;
    const int2* bp = esw + (size_t)node * PAD;
    for (int j = 0; j < m; j++) {
        int2 p = __ldg(bp + j);
        float w = __int_as_float(p.y);
        const float4* sr = reinterpret_cast<const float4*>(x + (size_t)p.x * D);
        float4 a = sr[lane];
        float4 b = sr[lane + 32];
        acc0.x = fmaf(w, a.x, acc0.x); acc0.y = fmaf(w, a.y, acc0.y);
        acc0.z = fmaf(w, a.z, acc0.z); acc0.w = fmaf(w, a.w, acc0.w);
        acc1.x = fmaf(w, b.x, acc1.x); acc1.y = fmaf(w, b.y, acc1.y);
        acc1.z = fmaf(w, b.z, acc1.z); acc1.w = fmaf(w, b.w, acc1.w);
    }
    if (mraw > PAD) {  // deterministic spill scan (expected count 0)
        int sc = *spill_cnt;
        if (sc > SPILL_MAX) sc = SPILL_MAX;
        for (int j = 0; j < sc; j++) {
            int4 e = spill[j];
            if (e.y != node) continue;
            float w = __int_as_float(e.z);
            const float4* sr = reinterpret_cast<const float4*>(x + (size_t)e.x * D);
            float4 a = sr[lane];
            float4 b = sr[lane + 32];
            acc0.x = fmaf(w, a.x, acc0.x); acc0.y = fmaf(w, a.y, acc0.y);
            acc0.z = fmaf(w, a.z, acc0.z); acc0.w = fmaf(w, a.w, acc0.w);
            acc1.x = fmaf(w, b.x, acc1.x); acc1.y = fmaf(w, b.y, acc1.y);
            acc1.z = fmaf(w, b.z, acc1.z); acc1.w = fmaf(w, b.w, acc1.w);
        }
    }
    size_t base = (size_t)node * D + lane * 4;
    wr_split(Ah + base, Al + base, acc0);
    wr_split(Ah + base + 128, Al + base + 128, acc1);
}

// ---------------------------------------------------------------------------
// Split-bf16 tensor-core GEMM + fused epilogue.
// Block 64(m) x 256(n), 8 warps (2m x 4n), warp tile 32x64, mma.m16n8k16.
// MODE 0: LN+GELU -> fp32 x.  MODE 1: LN+GELU -> bf16 hi/lo planes.
// MODE 2: +bias -> fp32 out.
// ---------------------------------------------------------------------------
#define MMA_BF16(c, a, b0, b1)                                                        \
    asm volatile(                                                                     \
        "mma.sync.aligned.m16n8k16.row.col.f32.bf16.bf16.f32 "                        \
        "{%0,%1,%2,%3}, {%4,%5,%6,%7}, {%8,%9}, {%0,%1,%2,%3};"                       \
        : "+f"(c[0]), "+f"(c[1]), "+f"(c[2]), "+f"(c[3])                              \
        : "r"(a[0]), "r"(a[1]), "r"(a[2]), "r"(a[3]), "r"(b0), "r"(b1))

template<int MODE>
__global__ void __launch_bounds__(256, 2)
hgemm_kernel(const __nv_bfloat16* __restrict__ Ah, const __nv_bfloat16* __restrict__ Al,
             const uint4* __restrict__ Bp, const float* __restrict__ bias,
             const float* __restrict__ gamma, const float* __restrict__ beta,
             float* __restrict__ xout, __nv_bfloat16* __restrict__ oh,
             __nv_bfloat16* __restrict__ ol, float* __restrict__ fout, int n) {
    __shared__ float red[64][4][2];

    int tid = threadIdx.x, lane = tid & 31, w = tid >> 5;
    int wn = w & 3, wm = w >> 2;
    int t = lane & 3, g = lane >> 2;
    int m0 = blockIdx.x * 64;
    int rbase = m0 + wm * 32 + g;

    float acc[2][8][4];
#pragma unroll
    for (int mt = 0; mt < 2; mt++)
#pragma unroll
        for (int nt = 0; nt < 8; nt++)
#pragma unroll
            for (int c = 0; c < 4; c++) acc[mt][nt][c] = 0.f;

    bool vr[2][2];
    vr[0][0] = rbase < n;       vr[0][1] = rbase + 8 < n;
    vr[1][0] = rbase + 16 < n;  vr[1][1] = rbase + 24 < n;

    for (int kt = 0; kt < 16; kt++) {
        int ka = kt * 16 + 2 * t;
        uint32_t ah[2][4], al[2][4];
#pragma unroll
        for (int mt = 0; mt < 2; mt++) {
            size_t r0 = (size_t)(rbase + mt * 16) * D;
            size_t r1 = r0 + 8 * D;
            ah[mt][0] = vr[mt][0] ? *reinterpret_cast<const uint32_t*>(Ah + r0 + ka) : 0u;
            ah[mt][1] = vr[mt][1] ? *reinterpret_cast<const uint32_t*>(Ah + r1 + ka) : 0u;
            ah[mt][2] = vr[mt][0] ? *reinterpret_cast<const uint32_t*>(Ah + r0 + ka + 8) : 0u;
            ah[mt][3] = vr[mt][1] ? *reinterpret_cast<const uint32_t*>(Ah + r1 + ka + 8) : 0u;
            al[mt][0] = vr[mt][0] ? *reinterpret_cast<const uint32_t*>(Al + r0 + ka) : 0u;
            al[mt][1] = vr[mt][1] ? *reinterpret_cast<const uint32_t*>(Al + r1 + ka) : 0u;
            al[mt][2] = vr[mt][0] ? *reinterpret_cast<const uint32_t*>(Al + r0 + ka + 8) : 0u;
            al[mt][3] = vr[mt][1] ? *reinterpret_cast<const uint32_t*>(Al + r1 + ka + 8) : 0u;
        }
#pragma unroll
        for (int nt = 0; nt < 8; nt++) {
            uint4 b = __ldg(Bp + ((size_t)(kt * 32 + wn * 8 + nt) << 5) + lane);
#pragma unroll
            for (int mt = 0; mt < 2; mt++) {
                MMA_BF16(acc[mt][nt], ah[mt], b.x, b.y);   // Ah*Bh
                MMA_BF16(acc[mt][nt], ah[mt], b.z, b.w);   // Ah*Bl
                MMA_BF16(acc[mt][nt], al[mt], b.x, b.y);   // Al*Bh
            }
        }
    }

    // ---- epilogue. cols for (nt): cb = wn*64 + nt*8 + 2t (pair cb, cb+1) ----
    if (MODE == 2) {
#pragma unroll
        for (int mt = 0; mt < 2; mt++)
#pragma unroll
            for (int half = 0; half < 2; half++) {
                int row = rbase + mt * 16 + half * 8;
                if (row >= n) continue;
#pragma unroll
                for (int nt = 0; nt < 8; nt++) {
                    int cb = wn * 64 + nt * 8 + 2 * t;
                    float2 bb = __ldg(reinterpret_cast<const float2*>(bias + cb));
                    float2 o;
                    o.x = acc[mt][nt][half * 2 + 0] + bb.x;
                    o.y = acc[mt][nt][half * 2 + 1] + bb.y;
                    *reinterpret_cast<float2*>(fout + (size_t)row * D + cb) = o;
                }
            }
        return;
    }

    float sm[4] = {0.f, 0.f, 0.f, 0.f}, sq[4] = {0.f, 0.f, 0.f, 0.f};
#pragma unroll
    for (int mt = 0; mt < 2; mt++)
#pragma unroll
        for (int nt = 0; nt < 8; nt++) {
            int cb = wn * 64 + nt * 8 + 2 * t;
            float2 bb = __ldg(reinterpret_cast<const float2*>(bias + cb));
            float v00 = acc[mt][nt][0] + bb.x, v01 = acc[mt][nt][1] + bb.y;
            float v10 = acc[mt][nt][2] + bb.x, v11 = acc[mt][nt][3] + bb.y;
            sm[mt * 2 + 0] += v00 + v01; sq[mt * 2 + 0] += v00 * v00 + v01 * v01;
            sm[mt * 2 + 1] += v10 + v11; sq[mt * 2 + 1] += v10 * v10 + v11 * v11;
        }
#pragma unroll
    for (int r = 0; r < 4; r++) {
#pragma unroll
        for (int o = 1; o < 4; o <<= 1) {
            sm[r] += __shfl_xor_sync(0xffffffffu, sm[r], o);
            sq[r] += __shfl_xor_sync(0xffffffffu, sq[r], o);
        }
    }
    if (t == 0) {
#pragma unroll
        for (int r = 0; r < 4; r++) {
            int lr = wm * 32 + (r >> 1) * 16 + (r & 1) * 8 + g;
            red[lr][wn][0] = sm[r];
            red[lr][wn][1] = sq[r];
        }
    }
    __syncthreads();
    float mean[4], rstd[4];
#pragma unroll
    for (int r = 0; r < 4; r++) {
        int lr = wm * 32 + (r >> 1) * 16 + (r & 1) * 8 + g;
        float S = 0.f, Q = 0.f;
#pragma unroll
        for (int j = 0; j < 4; j++) { S += red[lr][j][0]; Q += red[lr][j][1]; }
        float mu = S * (1.f / 256.f);
        mean[r] = mu;
        rstd[r] = rsqrtf(Q * (1.f / 256.f) - mu * mu + 1e-5f);
    }
#pragma unroll
    for (int mt = 0; mt < 2; mt++)
#pragma unroll
        for (int nt = 0; nt < 8; nt++) {
            int cb = wn * 64 + nt * 8 + 2 * t;
            float2 bb = __ldg(reinterpret_cast<const float2*>(bias + cb));
            float2 gg = __ldg(reinterpret_cast<const float2*>(gamma + cb));
            float2 be = __ldg(reinterpret_cast<const float2*>(beta + cb));
#pragma unroll
            for (int half = 0; half < 2; half++) {
                int row = rbase + mt * 16 + half * 8;
                if (row >= n) continue;
                int r = mt * 2 + half;
                float v0 = acc[mt][nt][half * 2 + 0] + bb.x;
                float v1 = acc[mt][nt][half * 2 + 1] + bb.y;
                float t0 = (v0 - mean[r]) * rstd[r] * gg.x + be.x;
                float t1 = (v1 - mean[r]) * rstd[r] * gg.y + be.y;
                float ge0 = 0.5f * t0 * (1.f + erff(t0 * 0.70710678118654752f));
                float ge1 = 0.5f * t1 * (1.f + erff(t1 * 0.70710678118654752f));
                if (MODE == 0) {
                    float2 o; o.x = ge0; o.y = ge1;
                    *reinterpret_cast<float2*>(xout + (size_t)row * D + cb) = o;
                } else {
                    __nv_bfloat16 h0 = __float2bfloat16_rn(ge0);
                    __nv_bfloat16 h1 = __float2bfloat16_rn(ge1);
                    __nv_bfloat16 l0 = __float2bfloat16_rn(ge0 - __bfloat162float(h0));
                    __nv_bfloat16 l1 = __float2bfloat16_rn(ge1 - __bfloat162float(h1));
                    *reinterpret_cast<uint32_t*>(oh + (size_t)row * D + cb) = pk(h0, h1);
                    *reinterpret_cast<uint32_t*>(ol + (size_t)row * D + cb) = pk(l0, l1);
                }
            }
        }
}

// ---------------------------------------------------------------------------
// launch
// ---------------------------------------------------------------------------
extern "C" void kernel_launch(void* const* d_in, const int* in_sizes, int n_in,
                              void* d_out, int out_size) {
    const float* node = (const float*)d_in[0];
    const int*   src  = (const int*)d_in[1];
    const int*   dst  = (const int*)d_in[2];
    const float* ew   = (const float*)d_in[3];
    const float* W1   = (const float*)d_in[4];
    const float* b1   = (const float*)d_in[5];
    const float* g1   = (const float*)d_in[6];
    const float* be1  = (const float*)d_in[7];
    const float* W2   = (const float*)d_in[8];
    const float* b2   = (const float*)d_in[9];
    const float* g2   = (const float*)d_in[10];
    const float* be2  = (const float*)d_in[11];
    const float* Wp   = (const float*)d_in[12];
    const float* bp   = (const float*)d_in[13];
    float* out = (float*)d_out;

    int n = in_sizes[0] / D;
    int nedges = in_sizes[1];

    __nv_bfloat16 *ah, *al, *ch, *cl;
    float* x;
    int *cnt, *spill_cnt;
    int2* esw;
    int4* spill;
    uint4 *bp1, *bp2, *bp3;
    cudaGetSymbolAddress((void**)&ah, g_ah);
    cudaGetSymbolAddress((void**)&al, g_al);
    cudaGetSymbolAddress((void**)&ch, g_ch);
    cudaGetSymbolAddress((void**)&cl, g_cl);
    cudaGetSymbolAddress((void**)&x, g_x);
    cudaGetSymbolAddress((void**)&cnt, g_cnt);
    cudaGetSymbolAddress((void**)&esw, g_esw);
    cudaGetSymbolAddress((void**)&spill, g_spill);
    cudaGetSymbolAddress((void**)&spill_cnt, g_spill_cnt);
    cudaGetSymbolAddress((void**)&bp1, g_bp1);
    cudaGetSymbolAddress((void**)&bp2, g_bp2);
    cudaGetSymbolAddress((void**)&bp3, g_bp3);

    int edgeBlocks = (nedges + 255) / 256;
    int spmmBlocks = (n + 7) / 8;
    int gemmBlocks = (n + 63) / 64;
    int prepBlocks = (16 * 32 * 32 + 255) / 256;

    // ---- build + weight prep ----
    cudaMemsetAsync(cnt, 0, (size_t)n * sizeof(int));
    cudaMemsetAsync(spill_cnt, 0, sizeof(int));
    bucket_kernel<<<edgeBlocks, 256>>>(src, dst, ew, cnt, esw, spill, spill_cnt, nedges);
    prep_b_kernel<<<prepBlocks, 256>>>(W1, bp1);
    prep_b_kernel<<<prepBlocks, 256>>>(W2, bp2);
    prep_b_kernel<<<prepBlocks, 256>>>(Wp, bp3);

    // ---- Layer 1: spmm(node) -> planes; gemm -> fp32 x ----
    spmm_kernel<<<spmmBlocks, 256>>>(node, esw, cnt, spill, spill_cnt, ah, al, n);
    hgemm_kernel<0><<<gemmBlocks, 256>>>(ah, al, bp1, b1, g1, be1, x, nullptr, nullptr, nullptr, n);

    // ---- Layer 2: spmm(x) -> planes; gemm -> planes ----
    spmm_kernel<<<spmmBlocks, 256>>>(x, esw, cnt, spill, spill_cnt, ah, al, n);
    hgemm_kernel<1><<<gemmBlocks, 256>>>(ah, al, bp2, b2, g2, be2, nullptr, ch, cl, nullptr, n);

    // ---- Projection: gemm(planes) -> out ----
    hgemm_kernel<2><<<gemmBlocks, 256>>>(ch, cl, bp3, bp, nullptr, nullptr, nullptr, nullptr, nullptr, out, n);
}

// round 7
// speedup vs baseline: 3.1209x; 1.1704x over previous
#include <cuda_runtime.h>
#include <cuda_bf16.h>
#include <math.h>
#include <stdint.h>

#define NN 50000
#define D 256
#define NE 800000
#define PAD 64
#define SPILL_MAX 8192

// ---------------------------------------------------------------------------
// Scratch (allocation-free rule: __device__ globals)
// ---------------------------------------------------------------------------
__device__ __nv_bfloat16 g_ah[(size_t)NN * D];   // activation hi plane
__device__ __nv_bfloat16 g_al[(size_t)NN * D];   // activation lo plane
__device__ __nv_bfloat16 g_ch[(size_t)NN * D];   // second plane pair
__device__ __nv_bfloat16 g_cl[(size_t)NN * D];
__device__ float g_x[(size_t)NN * D];            // fp32 layer-1 output (SPMM2 input)
__device__ int   g_cnt[NN];
__device__ int2  g_esw[(size_t)NN * PAD];
__device__ int4  g_spill[SPILL_MAX];
__device__ int   g_spill_cnt;
__device__ uint4 g_bp1[16 * 32 * 32];            // fragment-packed weights hi|lo
__device__ uint4 g_bp2[16 * 32 * 32];
__device__ uint4 g_bp3[16 * 32 * 32];

__device__ __forceinline__ uint32_t pk(__nv_bfloat16 a, __nv_bfloat16 b) {
    return (uint32_t)__bfloat16_as_ushort(a) | ((uint32_t)__bfloat16_as_ushort(b) << 16);
}

// ---------------------------------------------------------------------------
// Bucket build (one pass)
// ---------------------------------------------------------------------------
__global__ void bucket_kernel(const int* __restrict__ src, const int* __restrict__ dst,
                              const float* __restrict__ ew, int* __restrict__ cnt,
                              int2* __restrict__ esw, int4* __restrict__ spill,
                              int* __restrict__ spill_cnt, int ne) {
    int e = blockIdx.x * blockDim.x + threadIdx.x;
    if (e >= ne) return;
    int d = dst[e];
    int s = src[e];
    int wb = __float_as_int(ew[e]);
    int pos = atomicAdd(cnt + d, 1);
    if (pos < PAD) {
        esw[(size_t)d * PAD + pos] = make_int2(s, wb);
    } else {
        int sp = atomicAdd(spill_cnt, 1);
        if (sp < SPILL_MAX) spill[sp] = make_int4(s, d, wb, 0);
    }
}

// ---------------------------------------------------------------------------
// Weight prep (all three matrices in one launch, grid.y selects matrix).
// idx = (kt*32 + ntile)*32 + lane ; lane: t=lane&3 (k-pair), g=lane>>2 (n).
// uint4 = { hi(k=2t,2t+1), hi(k=2t+8,2t+9), lo(k=2t,2t+1), lo(k=2t+8,2t+9) }
// ---------------------------------------------------------------------------
__global__ void prep_b_kernel(const float* __restrict__ Wa, const float* __restrict__ Wb,
                              const float* __restrict__ Wc, uint4* __restrict__ pa,
                              uint4* __restrict__ pb, uint4* __restrict__ pc) {
    const float* W = (blockIdx.y == 0) ? Wa : (blockIdx.y == 1) ? Wb : Wc;
    uint4* bp = (blockIdx.y == 0) ? pa : (blockIdx.y == 1) ? pb : pc;
    int idx = blockIdx.x * 256 + threadIdx.x;
    if (idx >= 16 * 32 * 32) return;
    int lane = idx & 31, ntg = (idx >> 5) & 31, kt = idx >> 10;
    int t = lane & 3, g = lane >> 2;
    int nn = ntg * 8 + g;
    int k0 = kt * 16 + 2 * t;
    float w0 = W[(size_t)k0 * D + nn];
    float w1 = W[(size_t)(k0 + 1) * D + nn];
    float w2 = W[(size_t)(k0 + 8) * D + nn];
    float w3 = W[(size_t)(k0 + 9) * D + nn];
    __nv_bfloat16 h0 = __float2bfloat16_rn(w0), h1 = __float2bfloat16_rn(w1);
    __nv_bfloat16 h2 = __float2bfloat16_rn(w2), h3 = __float2bfloat16_rn(w3);
    __nv_bfloat16 l0 = __float2bfloat16_rn(w0 - __bfloat162float(h0));
    __nv_bfloat16 l1 = __float2bfloat16_rn(w1 - __bfloat162float(h1));
    __nv_bfloat16 l2 = __float2bfloat16_rn(w2 - __bfloat162float(h2));
    __nv_bfloat16 l3 = __float2bfloat16_rn(w3 - __bfloat162float(h3));
    uint4 v;
    v.x = pk(h0, h1); v.y = pk(h2, h3);
    v.z = pk(l0, l1); v.w = pk(l2, l3);
    bp[idx] = v;
}

// ---------------------------------------------------------------------------
// SPMM + residual -> bf16 hi/lo planes. One warp per node, no atomics.
// ---------------------------------------------------------------------------
__device__ __forceinline__ void wr_split(__nv_bfloat16* Hp, __nv_bfloat16* Lp, float4 a) {
    __nv_bfloat16 h0 = __float2bfloat16_rn(a.x), h1 = __float2bfloat16_rn(a.y);
    __nv_bfloat16 h2 = __float2bfloat16_rn(a.z), h3 = __float2bfloat16_rn(a.w);
    __nv_bfloat16 l0 = __float2bfloat16_rn(a.x - __bfloat162float(h0));
    __nv_bfloat16 l1 = __float2bfloat16_rn(a.y - __bfloat162float(h1));
    __nv_bfloat16 l2 = __float2bfloat16_rn(a.z - __bfloat162float(h2));
    __nv_bfloat16 l3 = __float2bfloat16_rn(a.w - __bfloat162float(h3));
    uint2 uh, ul;
    uh.x = pk(h0, h1); uh.y = pk(h2, h3);
    ul.x = pk(l0, l1); ul.y = pk(l2, l3);
    *reinterpret_cast<uint2*>(Hp) = uh;
    *reinterpret_cast<uint2*>(Lp) = ul;
}

__global__ void __launch_bounds__(256)
spmm_kernel(const float* __restrict__ x, const int2* __restrict__ esw,
            const int* __restrict__ cnt, const int4* __restrict__ spill,
            const int* __restrict__ spill_cnt,
            __nv_bfloat16* __restrict__ Ah, __nv_bfloat16* __restrict__ Al, int n) {
    int node = (blockIdx.x * blockDim.x + threadIdx.x) >> 5;
    if (node >= n) return;
    int lane = threadIdx.x & 31;

    const float4* xr = reinterpret_cast<const float4*>(x + (size_t)node * D);
    float4 acc0 = xr[lane];
    float4 acc1 = xr[lane + 32];

    int mraw = cnt[node];
    int m = mraw < PAD ? mraw : PAD;
    const int2* bp = esw + (size_t)node * PAD;
    for (int j = 0; j < m; j++) {
        int2 p = __ldg(bp + j);
        float w = __int_as_float(p.y);
        const float4* sr = reinterpret_cast<const float4*>(x + (size_t)p.x * D);
        float4 a = sr[lane];
        float4 b = sr[lane + 32];
        acc0.x = fmaf(w, a.x, acc0.x); acc0.y = fmaf(w, a.y, acc0.y);
        acc0.z = fmaf(w, a.z, acc0.z); acc0.w = fmaf(w, a.w, acc0.w);
        acc1.x = fmaf(w, b.x, acc1.x); acc1.y = fmaf(w, b.y, acc1.y);
        acc1.z = fmaf(w, b.z, acc1.z); acc1.w = fmaf(w, b.w, acc1.w);
    }
    if (mraw > PAD) {  // deterministic spill scan (expected count 0)
        int sc = *spill_cnt;
        if (sc > SPILL_MAX) sc = SPILL_MAX;
        for (int j = 0; j < sc; j++) {
            int4 e = spill[j];
            if (e.y != node) continue;
            float w = __int_as_float(e.z);
            const float4* sr = reinterpret_cast<const float4*>(x + (size_t)e.x * D);
            float4 a = sr[lane];
            float4 b = sr[lane + 32];
            acc0.x = fmaf(w, a.x, acc0.x); acc0.y = fmaf(w, a.y, acc0.y);
            acc0.z = fmaf(w, a.z, acc0.z); acc0.w = fmaf(w, a.w, acc0.w);
            acc1.x = fmaf(w, b.x, acc1.x); acc1.y = fmaf(w, b.y, acc1.y);
            acc1.z = fmaf(w, b.z, acc1.z); acc1.w = fmaf(w, b.w, acc1.w);
        }
    }
    size_t base = (size_t)node * D + lane * 4;
    wr_split(Ah + base, Al + base, acc0);
    wr_split(Ah + base + 128, Al + base + 128, acc1);
}

// ---------------------------------------------------------------------------
// Split-bf16 tensor-core GEMM + fused epilogue.
// Block 64(m) x 256(n), 8 warps (2m x 4n), warp tile 32x64, mma.m16n8k16.
// A tile staged in smem (pitch 264 elems = 528B -> bank = 4g+t, conflict-free).
// MODE 0: LN+GELU -> fp32 x. MODE 1: LN+GELU -> bf16 planes. MODE 2: +bias -> fp32.
// ---------------------------------------------------------------------------
#define APITCH 264                          // elems; 132 uint32 words per row
#define ASMEM_ELEMS (64 * APITCH)           // one plane
#define ASMEM_BYTES (2 * ASMEM_ELEMS * 2)   // hi + lo, bf16

#define MMA_BF16(c, a, b0, b1)                                                        \
    asm volatile(                                                                     \
        "mma.sync.aligned.m16n8k16.row.col.f32.bf16.bf16.f32 "                        \
        "{%0,%1,%2,%3}, {%4,%5,%6,%7}, {%8,%9}, {%0,%1,%2,%3};"                       \
        : "+f"(c[0]), "+f"(c[1]), "+f"(c[2]), "+f"(c[3])                              \
        : "r"(a[0]), "r"(a[1]), "r"(a[2]), "r"(a[3]), "r"(b0), "r"(b1))

template<int MODE>
__global__ void __launch_bounds__(256, 2)
hgemm_kernel(const __nv_bfloat16* __restrict__ Ah, const __nv_bfloat16* __restrict__ Al,
             const uint4* __restrict__ Bp, const float* __restrict__ bias,
             const float* __restrict__ gamma, const float* __restrict__ beta,
             float* __restrict__ xout, __nv_bfloat16* __restrict__ oh,
             __nv_bfloat16* __restrict__ ol, float* __restrict__ fout, int n) {
    extern __shared__ __nv_bfloat16 sA[];        // [hi | lo], 64 rows, pitch APITCH
    __shared__ float red[64][4][2];

    int tid = threadIdx.x, lane = tid & 31, w = tid >> 5;
    int wn = w & 3, wm = w >> 2;
    int t = lane & 3, g = lane >> 2;
    int m0 = blockIdx.x * 64;
    int rbase = m0 + wm * 32 + g;

    // ---- cooperative A-tile load (hi+lo), fully coalesced ----
    {
        __nv_bfloat16* sAh = sA;
        __nv_bfloat16* sAl = sA + ASMEM_ELEMS;
#pragma unroll
        for (int i = 0; i < 16; i++) {
            int idx = tid + 256 * i;          // 0..4095
            int plane = idx >> 11;            // 0 = hi, 1 = lo
            int j = idx & 2047;
            int r = j >> 5, q = j & 31;       // row 0..63, uint4 index 0..31
            int gr = m0 + r;
            uint4 v = make_uint4(0u, 0u, 0u, 0u);
            const __nv_bfloat16* sp = plane ? Al : Ah;
            if (gr < n) v = *reinterpret_cast<const uint4*>(sp + (size_t)gr * D + q * 8);
            __nv_bfloat16* dp = plane ? sAl : sAh;
            *reinterpret_cast<uint4*>(dp + r * APITCH + q * 8) = v;
        }
    }
    __syncthreads();

    const uint32_t* sh32 = reinterpret_cast<const uint32_t*>(sA);
    const uint32_t* sl32 = reinterpret_cast<const uint32_t*>(sA) + ASMEM_ELEMS / 2;
    int arow = wm * 32 + g;                   // local row of a0/a2

    float acc[2][8][4];
#pragma unroll
    for (int mt = 0; mt < 2; mt++)
#pragma unroll
        for (int nt = 0; nt < 8; nt++)
#pragma unroll
            for (int c = 0; c < 4; c++) acc[mt][nt][c] = 0.f;

    const uint4* bwarp = Bp + (size_t)(wn * 8) * 32 + lane;

#pragma unroll
    for (int kt = 0; kt < 16; kt++) {
        int ko = kt * 8 + t;                  // uint32 offset within row
        uint32_t ah[2][4], al[2][4];
#pragma unroll
        for (int mt = 0; mt < 2; mt++) {
            int r0 = (arow + mt * 16) * 132;
            int r1 = r0 + 8 * 132;
            ah[mt][0] = sh32[r0 + ko];
            ah[mt][1] = sh32[r1 + ko];
            ah[mt][2] = sh32[r0 + ko + 4];
            ah[mt][3] = sh32[r1 + ko + 4];
            al[mt][0] = sl32[r0 + ko];
            al[mt][1] = sl32[r1 + ko];
            al[mt][2] = sl32[r0 + ko + 4];
            al[mt][3] = sl32[r1 + ko + 4];
        }
        const uint4* bk = bwarp + (size_t)(kt * 32) * 32;
        uint4 bcur = __ldg(bk);
#pragma unroll
        for (int nt = 0; nt < 8; nt++) {
            uint4 bnext = (nt < 7) ? __ldg(bk + (size_t)(nt + 1) * 32) : bcur;
#pragma unroll
            for (int mt = 0; mt < 2; mt++) {
                MMA_BF16(acc[mt][nt], ah[mt], bcur.x, bcur.y);   // Ah*Bh
                MMA_BF16(acc[mt][nt], ah[mt], bcur.z, bcur.w);   // Ah*Bl
                MMA_BF16(acc[mt][nt], al[mt], bcur.x, bcur.y);   // Al*Bh
            }
            bcur = bnext;
        }
    }

    // ---- epilogue. cols for (nt): cb = wn*64 + nt*8 + 2t (pair cb, cb+1) ----
    if (MODE == 2) {
#pragma unroll
        for (int mt = 0; mt < 2; mt++)
#pragma unroll
            for (int half = 0; half < 2; half++) {
                int row = rbase + mt * 16 + half * 8;
                if (row >= n) continue;
#pragma unroll
                for (int nt = 0; nt < 8; nt++) {
                    int cb = wn * 64 + nt * 8 + 2 * t;
                    float2 bb = __ldg(reinterpret_cast<const float2*>(bias + cb));
                    float2 o;
                    o.x = acc[mt][nt][half * 2 + 0] + bb.x;
                    o.y = acc[mt][nt][half * 2 + 1] + bb.y;
                    *reinterpret_cast<float2*>(fout + (size_t)row * D + cb) = o;
                }
            }
        return;
    }

    float sm[4] = {0.f, 0.f, 0.f, 0.f}, sq[4] = {0.f, 0.f, 0.f, 0.f};
#pragma unroll
    for (int mt = 0; mt < 2; mt++)
#pragma unroll
        for (int nt = 0; nt < 8; nt++) {
            int cb = wn * 64 + nt * 8 + 2 * t;
            float2 bb = __ldg(reinterpret_cast<const float2*>(bias + cb));
            float v00 = acc[mt][nt][0] + bb.x, v01 = acc[mt][nt][1] + bb.y;
            float v10 = acc[mt][nt][2] + bb.x, v11 = acc[mt][nt][3] + bb.y;
            sm[mt * 2 + 0] += v00 + v01; sq[mt * 2 + 0] += v00 * v00 + v01 * v01;
            sm[mt * 2 + 1] += v10 + v11; sq[mt * 2 + 1] += v10 * v10 + v11 * v11;
        }
#pragma unroll
    for (int r = 0; r < 4; r++) {
#pragma unroll
        for (int o = 1; o < 4; o <<= 1) {
            sm[r] += __shfl_xor_sync(0xffffffffu, sm[r], o);
            sq[r] += __shfl_xor_sync(0xffffffffu, sq[r], o);
        }
    }
    if (t == 0) {
#pragma unroll
        for (int r = 0; r < 4; r++) {
            int lr = wm * 32 + (r >> 1) * 16 + (r & 1) * 8 + g;
            red[lr][wn][0] = sm[r];
            red[lr][wn][1] = sq[r];
        }
    }
    __syncthreads();
    float mean[4], rstd[4];
#pragma unroll
    for (int r = 0; r < 4; r++) {
        int lr = wm * 32 + (r >> 1) * 16 + (r & 1) * 8 + g;
        float S = 0.f, Q = 0.f;
#pragma unroll
        for (int j = 0; j < 4; j++) { S += red[lr][j][0]; Q += red[lr][j][1]; }
        float mu = S * (1.f / 256.f);
        mean[r] = mu;
        rstd[r] = rsqrtf(Q * (1.f / 256.f) - mu * mu + 1e-5f);
    }
#pragma unroll
    for (int mt = 0; mt < 2; mt++)
#pragma unroll
        for (int nt = 0; nt < 8; nt++) {
            int cb = wn * 64 + nt * 8 + 2 * t;
            float2 bb = __ldg(reinterpret_cast<const float2*>(bias + cb));
            float2 gg = __ldg(reinterpret_cast<const float2*>(gamma + cb));
            float2 be = __ldg(reinterpret_cast<const float2*>(beta + cb));
#pragma unroll
            for (int half = 0; half < 2; half++) {
                int row = rbase + mt * 16 + half * 8;
                if (row >= n) continue;
                int r = mt * 2 + half;
                float v0 = acc[mt][nt][half * 2 + 0] + bb.x;
                float v1 = acc[mt][nt][half * 2 + 1] + bb.y;
                float t0 = (v0 - mean[r]) * rstd[r] * gg.x + be.x;
                float t1 = (v1 - mean[r]) * rstd[r] * gg.y + be.y;
                float ge0 = 0.5f * t0 * (1.f + erff(t0 * 0.70710678118654752f));
                float ge1 = 0.5f * t1 * (1.f + erff(t1 * 0.70710678118654752f));
                if (MODE == 0) {
                    float2 o; o.x = ge0; o.y = ge1;
                    *reinterpret_cast<float2*>(xout + (size_t)row * D + cb) = o;
                } else {
                    __nv_bfloat16 h0 = __float2bfloat16_rn(ge0);
                    __nv_bfloat16 h1 = __float2bfloat16_rn(ge1);
                    __nv_bfloat16 l0 = __float2bfloat16_rn(ge0 - __bfloat162float(h0));
                    __nv_bfloat16 l1 = __float2bfloat16_rn(ge1 - __bfloat162float(h1));
                    *reinterpret_cast<uint32_t*>(oh + (size_t)row * D + cb) = pk(h0, h1);
                    *reinterpret_cast<uint32_t*>(ol + (size_t)row * D + cb) = pk(l0, l1);
                }
            }
        }
}

// ---------------------------------------------------------------------------
// launch
// ---------------------------------------------------------------------------
extern "C" void kernel_launch(void* const* d_in, const int* in_sizes, int n_in,
                              void* d_out, int out_size) {
    const float* node = (const float*)d_in[0];
    const int*   src  = (const int*)d_in[1];
    const int*   dst  = (const int*)d_in[2];
    const float* ew   = (const float*)d_in[3];
    const float* W1   = (const float*)d_in[4];
    const float* b1   = (const float*)d_in[5];
    const float* g1   = (const float*)d_in[6];
    const float* be1  = (const float*)d_in[7];
    const float* W2   = (const float*)d_in[8];
    const float* b2   = (const float*)d_in[9];
    const float* g2   = (const float*)d_in[10];
    const float* be2  = (const float*)d_in[11];
    const float* Wp   = (const float*)d_in[12];
    const float* bp   = (const float*)d_in[13];
    float* out = (float*)d_out;

    int n = in_sizes[0] / D;
    int nedges = in_sizes[1];

    __nv_bfloat16 *ah, *al, *ch, *cl;
    float* x;
    int *cnt, *spill_cnt;
    int2* esw;
    int4* spill;
    uint4 *bp1, *bp2, *bp3;
    cudaGetSymbolAddress((void**)&ah, g_ah);
    cudaGetSymbolAddress((void**)&al, g_al);
    cudaGetSymbolAddress((void**)&ch, g_ch);
    cudaGetSymbolAddress((void**)&cl, g_cl);
    cudaGetSymbolAddress((void**)&x, g_x);
    cudaGetSymbolAddress((void**)&cnt, g_cnt);
    cudaGetSymbolAddress((void**)&esw, g_esw);
    cudaGetSymbolAddress((void**)&spill, g_spill);
    cudaGetSymbolAddress((void**)&spill_cnt, g_spill_cnt);
    cudaGetSymbolAddress((void**)&bp1, g_bp1);
    cudaGetSymbolAddress((void**)&bp2, g_bp2);
    cudaGetSymbolAddress((void**)&bp3, g_bp3);

    cudaFuncSetAttribute(hgemm_kernel<0>, cudaFuncAttributeMaxDynamicSharedMemorySize, ASMEM_BYTES);
    cudaFuncSetAttribute(hgemm_kernel<1>, cudaFuncAttributeMaxDynamicSharedMemorySize, ASMEM_BYTES);
    cudaFuncSetAttribute(hgemm_kernel<2>, cudaFuncAttributeMaxDynamicSharedMemorySize, ASMEM_BYTES);

    int edgeBlocks = (nedges + 255) / 256;
    int spmmBlocks = (n + 7) / 8;
    int gemmBlocks = (n + 63) / 64;
    dim3 prepGrid((16 * 32 * 32 + 255) / 256, 3);

    // ---- build + weight prep ----
    cudaMemsetAsync(cnt, 0, (size_t)n * sizeof(int));
    cudaMemsetAsync(spill_cnt, 0, sizeof(int));
    bucket_kernel<<<edgeBlocks, 256>>>(src, dst, ew, cnt, esw, spill, spill_cnt, nedges);
    prep_b_kernel<<<prepGrid, 256>>>(W1, W2, Wp, bp1, bp2, bp3);

    // ---- Layer 1: spmm(node) -> planes; gemm -> fp32 x ----
    spmm_kernel<<<spmmBlocks, 256>>>(node, esw, cnt, spill, spill_cnt, ah, al, n);
    hgemm_kernel<0><<<gemmBlocks, 256, ASMEM_BYTES>>>(ah, al, bp1, b1, g1, be1, x, nullptr, nullptr, nullptr, n);

    // ---- Layer 2: spmm(x) -> planes; gemm -> planes ----
    spmm_kernel<<<spmmBlocks, 256>>>(x, esw, cnt, spill, spill_cnt, ah, al, n);
    hgemm_kernel<1><<<gemmBlocks, 256, ASMEM_BYTES>>>(ah, al, bp2, b2, g2, be2, nullptr, ch, cl, nullptr, n);

    // ---- Projection: gemm(planes) -> out ----
    hgemm_kernel<2><<<gemmBlocks, 256, ASMEM_BYTES>>>(ch, cl, bp3, bp, nullptr, nullptr, nullptr, nullptr, nullptr, out, n);
}